// round 11
// baseline (speedup 1.0000x reference)
#include <cuda_runtime.h>
#include <cuda_bf16.h>
#include <mma.h>
#include <math.h>

using namespace nvcuda;

#define VOCAB 32000
#define EMBED 512
#define HID   1024      // DEC_H
#define SEQL  64
#define BATCH 32
#define G4    4096
#define GRID  148
#define TPB   256
#define PAD   8

#define T_ENC 64        // G4/64 tiles
#define T_DEC 64
#define T_CMB 16        // HID/64
#define T_OUT 500       // VOCAB/64

#define CH    128       // K-chunk rows per pipeline stage
#define BSTG  4         // B pipeline stages
#define BLD   72        // padded B stage ld (bank-conflict-free)

// fixed smem layout (bytes): sA | sB ring | sC
#define SA_BYTES 131584                      // 32 * (2048+8) * 2
#define SB_BYTES (BSTG * CH * BLD * 2)       // 73728
#define SMEM_DYN (SA_BYTES + SB_BYTES + 32 * 64 * 4)   // 213504

typedef __nv_bfloat16 bf16;

// ---------------- device scratch ----------------
__device__ bf16  d_Eenc[SEQL * BATCH * EMBED];        // [t][b][e] bf16
__device__ bf16  d_enc_outs[BATCH * SEQL * HID];      // [b][t][d] bf16
__device__ bf16  d_gb0[BATCH * HID], d_gb1[BATCH * HID];   // encoder h ping-pong (bf16)
__device__ float d_ce[BATCH * HID];
__device__ bf16  d_hb0[BATCH * HID], d_hb1[BATCH * HID];   // decoder h ping-pong (bf16)
__device__ float d_cd[BATCH * HID];
__device__ bf16  d_ebuf[BATCH * HID];
__device__ bf16  d_ctx[BATCH * HID];
__device__ bf16  d_inp[BATCH * HID];
__device__ float d_logits[(size_t)BATCH * VOCAB];
__device__ float d_benc[G4], d_bdec[G4];
__device__ float d_pm[BATCH * 512], d_ps[BATCH * 512];
__device__ int   d_pa[BATCH * 512];
__device__ float d_lse[BATCH];
__device__ unsigned g_bar;       // full-grid barrier counter
__device__ unsigned g_bar_enc;   // 64-block encoder barrier counter

__device__ bf16 d_attnT[SEQL * 2 * HID];              // attn_w transposed: [l][k] bf16

__device__ bf16 d_Wenc[(size_t)T_ENC * (EMBED + HID) * 64];  // [tile][k][64], gate-interleaved cols
__device__ bf16 d_Wdec[(size_t)T_DEC * (2 * HID) * 64];
__device__ bf16 d_Wcmb[(size_t)T_CMB * (2 * HID) * 64];
__device__ bf16 d_Wout[(size_t)T_OUT * HID * 64];

__device__ __forceinline__ float sigm(float x) { return 1.f / (1.f + expf(-x)); }

__device__ __forceinline__ float dot8(uint4 ua, uint4 uw) {
    float s = 0.f;
    const unsigned* a = (const unsigned*)&ua;
    const unsigned* w = (const unsigned*)&uw;
    #pragma unroll
    for (int j = 0; j < 4; j++) {
        float2 fa = __bfloat1622float2(*(const __nv_bfloat162*)&a[j]);
        float2 fw = __bfloat1622float2(*(const __nv_bfloat162*)&w[j]);
        s += fa.x * fw.x + fa.y * fw.y;
    }
    return s;
}

// ---------------- cp.async helpers ----------------
__device__ __forceinline__ void cp_async16(bf16* smem_dst, const bf16* gmem_src) {
    unsigned d = (unsigned)__cvta_generic_to_shared(smem_dst);
    asm volatile("cp.async.cg.shared.global [%0], [%1], 16;\n" :: "r"(d), "l"(gmem_src));
}
__device__ __forceinline__ void cp_commit() { asm volatile("cp.async.commit_group;\n"); }
template<int N>
__device__ __forceinline__ void cp_wait() { asm volatile("cp.async.wait_group %0;\n" :: "n"(N)); }

// ---------------- software barrier ----------------
__device__ __forceinline__ void sw_barrier(unsigned* ctr, unsigned& gen, unsigned nblk) {
    __threadfence();                       // release
    __syncthreads();
    if (threadIdx.x == 0) {
        unsigned target = (gen + 1u) * nblk;
        atomicAdd(ctr, 1u);
        int it = 0;
        while (*((volatile unsigned*)ctr) < target) { if (++it > 64) __nanosleep(64); }
        __threadfence();                   // acquire: invalidate this SM's L1D
    }
    gen++;
    __syncthreads();
}

// ---------------- A staging: bf16 copy 32 x (K1+K2) -> smem, ldm = K+PAD ----------------
template<int K1, int K2>
__device__ __forceinline__ void stage_A(bf16* sA, const bf16* __restrict__ A1,
                                        const bf16* __restrict__ A2) {
    constexpr int K = K1 + K2;
    constexpr int tot = 32 * K / 8;
    for (int i = threadIdx.x; i < tot; i += TPB) {
        int m = i / (K / 8);
        int k = (i - m * (K / 8)) * 8;
        const bf16* s = (K2 == 0 || k < K1) ? (A1 + m * K1 + k) : (A2 + m * K2 + (k - K1));
        *(uint4*)(sA + m * (K + PAD) + k) = *(const uint4*)s;
    }
    __syncthreads();
}

// ---------------- B chunk copy: CH rows x 64 cols bf16 -> stage (CH x BLD) ----------------
__device__ __forceinline__ void copy_B_chunk(bf16* dst, const bf16* __restrict__ src) {
    const int tid = threadIdx.x;
    #pragma unroll
    for (int i = 0; i < CH * 64 / (8 * TPB); i++) {   // 4 iters: 1024 16B segments
        int idx = tid + i * TPB;
        int r = idx >> 3, cq = idx & 7;
        cp_async16(dst + r * BLD + cq * 8, src + (size_t)r * 64 + cq * 8);
    }
}

// ---------------- GEMM tile, cp.async pipelined B: sC[32][64] = sA[32][K] @ Bt[K][64] ----
// One group committed per iteration (empty at tail) => wait_group<2> proves chunk c done.
template<int K>
__device__ __forceinline__ void gemm_tile(const bf16* sA, const bf16* __restrict__ Bt,
                                          float* sC, bf16* sB) {
    constexpr int LDA = K + PAD;
    constexpr int NCH = K / CH;
    const int w = threadIdx.x >> 5;
    const int mh = w >> 2, nq = w & 3;

    // prologue: chunks 0..2
    #pragma unroll
    for (int st = 0; st < 3; st++) {
        copy_B_chunk(sB + st * (CH * BLD), Bt + (size_t)st * CH * 64);
        cp_commit();
    }

    wmma::fragment<wmma::matrix_a, 16, 16, 16, bf16, wmma::row_major> fa;
    wmma::fragment<wmma::matrix_b, 16, 16, 16, bf16, wmma::row_major> fb;
    wmma::fragment<wmma::accumulator, 16, 16, 16, float> acc[4];
    #pragma unroll
    for (int i = 0; i < 4; i++) wmma::fill_fragment(acc[i], 0.f);

    for (int c = 0; c < NCH; c++) {
        cp_wait<2>();          // chunk c's group (and older) complete
        __syncthreads();       // copies visible to all; all warps done with chunk c-1
        if (c + 3 < NCH)       // slot (c+3)&3 == (c-1)&3: safe after the sync above
            copy_B_chunk(sB + ((c + 3) & 3) * (CH * BLD), Bt + (size_t)(c + 3) * CH * 64);
        cp_commit();           // unconditionally: keeps group count = 1/iteration
        const bf16* bst = sB + (c & 3) * (CH * BLD) + nq * 16;
        const bf16* ast = sA + mh * 16 * LDA + c * CH;
        #pragma unroll
        for (int kk = 0; kk < CH / 16; kk++) {
            wmma::load_matrix_sync(fa, ast + kk * 16, LDA);
            wmma::load_matrix_sync(fb, bst + kk * 16 * BLD, BLD);
            wmma::mma_sync(acc[kk & 3], fa, fb, acc[kk & 3]);
        }
    }
    cp_wait<0>();
    #pragma unroll
    for (int i = 0; i < acc[0].num_elements; i++)
        acc[0].x[i] += acc[1].x[i] + acc[2].x[i] + acc[3].x[i];
    wmma::store_matrix_sync(sC + mh * 16 * 64 + nq * 16, acc[0], 64, wmma::mem_row_major);
    __syncthreads();
}

// ---------------- LSTM cell epilogue (interleaved gates, tile n0) ----------------
__device__ __forceinline__ void cell_epi(const float* sC, const float* bias, int n0,
                                         float* cbuf, bf16* hb, bf16* enc_out, int t) {
    for (int i = threadIdx.x; i < BATCH * 16; i += TPB) {
        int m = i >> 4, dd = i & 15, cb = dd * 4;
        float gi = sigm(sC[m * 64 + cb + 0] + bias[n0 + cb + 0]);
        float gf = sigm(sC[m * 64 + cb + 1] + bias[n0 + cb + 1]);
        float gg = tanhf(sC[m * 64 + cb + 2] + bias[n0 + cb + 2]);
        float go = sigm(sC[m * 64 + cb + 3] + bias[n0 + cb + 3]);
        int d = (n0 >> 2) + dd;
        int idx = m * HID + d;
        float c = gf * cbuf[idx] + gi * gg;
        float h = go * tanhf(c);
        cbuf[idx] = c;
        bf16 hb16 = __float2bfloat16(h);
        hb[idx] = hb16;
        if (enc_out) enc_out[((size_t)m * SEQL + t) * HID + d] = hb16;
    }
    __syncthreads();
}

// ---------------- out-projection epilogue: logits + online-softmax partials ----------------
__device__ __forceinline__ void epi_out(const float* sC, const float* __restrict__ out_b, int tile) {
    const int tid = threadIdx.x;
    const int r = tid >> 3, c0 = (tid & 7) * 8, n0 = tile * 64;
    float v[8];
    float pm = -INFINITY; int pa = 0;
    #pragma unroll
    for (int j = 0; j < 8; j++) {
        float x = sC[r * 64 + c0 + j] + out_b[n0 + c0 + j];
        v[j] = x;
        if (x > pm) { pm = x; pa = n0 + c0 + j; }
    }
    float4* dst = (float4*)(d_logits + (size_t)r * VOCAB + n0 + c0);
    dst[0] = make_float4(v[0], v[1], v[2], v[3]);
    dst[1] = make_float4(v[4], v[5], v[6], v[7]);
    float ps = 0.f;
    #pragma unroll
    for (int j = 0; j < 8; j++) ps += expf(v[j] - pm);
    #pragma unroll
    for (int o = 4; o > 0; o >>= 1) {
        float om = __shfl_xor_sync(0xffffffffu, pm, o);
        float os = __shfl_xor_sync(0xffffffffu, ps, o);
        int   oa = __shfl_xor_sync(0xffffffffu, pa, o);
        if (om > pm) { ps = ps * expf(pm - om) + os; pm = om; pa = oa; }
        else if (om == pm) { ps += os; if (oa < pa) pa = oa; }
        else ps += os * expf(om - pm);
    }
    if ((tid & 7) == 0) {
        d_pm[r * 512 + tile] = pm;
        d_ps[r * 512 + tile] = ps;
        d_pa[r * 512 + tile] = pa;
    }
    __syncthreads();
}

// ---------------- attention: logits + softmax + context for batch b (bf16 inputs) -------
__device__ void attn_phase(int b, const float* __restrict__ attn_b,
                           const bf16* __restrict__ hb, float* scratch) {
    float* aw = scratch;   // 64 floats
    const int tid = threadIdx.x;
    const int l = tid >> 2, part = tid & 3;
    const bf16* e = d_ebuf + b * HID;
    const bf16* h = hb + b * HID;
    const uint4* wrow = (const uint4*)(d_attnT + (size_t)l * 2 * HID + part * 512);
    const uint4* av = (const uint4*)((part < 2) ? (e + part * 512) : (h + (part - 2) * 512));
    float s = 0.f;
    #pragma unroll 8
    for (int i = 0; i < 64; i++) s += dot8(av[i], wrow[i]);
    s += __shfl_xor_sync(0xffffffffu, s, 1);
    s += __shfl_xor_sync(0xffffffffu, s, 2);
    if (part == 0) aw[l] = s + attn_b[l];
    __syncthreads();
    if (tid == 0) {
        float mx = -INFINITY;
        for (int j = 0; j < SEQL; j++) mx = fmaxf(mx, aw[j]);
        float sum = 0.f;
        for (int j = 0; j < SEQL; j++) { float ev = expf(aw[j] - mx); aw[j] = ev; sum += ev; }
        float inv = 1.f / sum;
        for (int j = 0; j < SEQL; j++) aw[j] *= inv;
    }
    __syncthreads();
    const bf16* eo = d_enc_outs + (size_t)b * SEQL * HID;
    const int d4 = tid * 4;
    float c0 = 0.f, c1 = 0.f, c2 = 0.f, c3 = 0.f;
    #pragma unroll 8
    for (int ll = 0; ll < SEQL; ll++) {
        float a = aw[ll];
        uint2 u = *(const uint2*)(eo + (size_t)ll * HID + d4);
        float2 p0 = __bfloat1622float2(*(const __nv_bfloat162*)&u.x);
        float2 p1 = __bfloat1622float2(*(const __nv_bfloat162*)&u.y);
        c0 += a * p0.x; c1 += a * p0.y; c2 += a * p1.x; c3 += a * p1.y;
    }
    __nv_bfloat162 o0 = __floats2bfloat162_rn(c0, c1);
    __nv_bfloat162 o1 = __floats2bfloat162_rn(c2, c3);
    uint2 uo; uo.x = *(unsigned*)&o0; uo.y = *(unsigned*)&o1;
    *(uint2*)(d_ctx + b * HID + d4) = uo;
    __syncthreads();
}

// ---------------- reduce partials -> lse, argmax token, gather next embedding ----------------
__device__ void reduce_phase(int b, const float* __restrict__ dec_embed, float* scratch) {
    const int tid = threadIdx.x;
    float* smax = scratch;
    float* ssum = scratch + 256;
    int*   sarg = (int*)(scratch + 512);
    int*   stok = (int*)(scratch + 768);
    float pm = -INFINITY, ps = 0.f; int pa = 0;
    for (int t = tid; t < T_OUT; t += TPB) {
        float om = d_pm[b * 512 + t], os = d_ps[b * 512 + t];
        int oa = d_pa[b * 512 + t];
        if (om > pm) { ps = ps * expf(pm - om) + os; pm = om; pa = oa; }
        else if (om == pm) { ps += os; if (oa < pa) pa = oa; }
        else ps += os * expf(om - pm);
    }
    smax[tid] = pm; ssum[tid] = ps; sarg[tid] = pa;
    __syncthreads();
    for (int st = 128; st > 0; st >>= 1) {
        if (tid < st) {
            float om = smax[tid + st], os = ssum[tid + st]; int oa = sarg[tid + st];
            float cm = smax[tid],      cs = ssum[tid];      int ca = sarg[tid];
            if (om > cm) { cs = cs * expf(cm - om) + os; cm = om; ca = oa; }
            else if (om == cm) { cs += os; if (oa < ca) ca = oa; }
            else cs += os * expf(om - cm);
            smax[tid] = cm; ssum[tid] = cs; sarg[tid] = ca;
        }
        __syncthreads();
    }
    if (tid == 0) { d_lse[b] = smax[0] + logf(ssum[0]); stok[0] = sarg[0]; }
    __syncthreads();
    int token = stok[0];
    for (int d = tid; d < HID; d += TPB)
        d_ebuf[b * HID + d] = __float2bfloat16(dec_embed[(size_t)token * HID + d]);
    __syncthreads();
}

// ---------------- distributed log-p write ----------------
__device__ void fixup_logp(int step, float* __restrict__ out, int bfirst, int nblocks) {
    int lb = blockIdx.x - bfirst;
    const int tot = BATCH * (VOCAB / 4);
    for (int i = lb * TPB + threadIdx.x; i < tot; i += nblocks * TPB) {
        int b = i / (VOCAB / 4);
        int q = i - b * (VOCAB / 4);
        float4 f = ((const float4*)(d_logits + (size_t)b * VOCAB))[q];
        float lse = d_lse[b];
        f.x -= lse; f.y -= lse; f.z -= lse; f.w -= lse;
        ((float4*)(out + ((size_t)b * SEQL + step) * VOCAB))[q] = f;
    }
}

// ---------------- persistent kernel ----------------
__global__ __launch_bounds__(TPB, 1) void seq_kernel(
    const float* __restrict__ attn_b,
    const float* __restrict__ comb_b, const float* __restrict__ out_b,
    const float* __restrict__ dec_embed, float* __restrict__ out)
{
    extern __shared__ unsigned char dynmem[];
    bf16*  sA = (bf16*)dynmem;
    bf16*  sB = (bf16*)(dynmem + SA_BYTES);
    float* sC = (float*)(dynmem + SA_BYTES + SB_BYTES);
    float* scratch = (float*)sA;
    unsigned gen = 0, gen_enc = 0;
    const int bid = blockIdx.x;

    // ---- encoder: blocks 0-63, sub-barrier of 64 ----
    if (bid < T_ENC) {
        for (int t = 0; t < SEQL; t++) {
            const bf16* hr = (t & 1) ? d_gb1 : d_gb0;
            bf16*       hw = (t & 1) ? d_gb0 : d_gb1;
            stage_A<EMBED, HID>(sA, d_Eenc + (size_t)t * BATCH * EMBED, hr);
            gemm_tile<EMBED + HID>(sA, d_Wenc + (size_t)bid * (EMBED + HID) * 64, sC, sB);
            cell_epi(sC, d_benc, bid * 64, d_ce, hw, d_enc_outs, t);
            sw_barrier(&g_bar_enc, gen_enc, T_ENC);
        }
    }
    sw_barrier(&g_bar, gen, GRID);

    // ---- decoder ----
    for (int s = 0; s < SEQL; s++) {
        const bf16* hr = (s & 1) ? d_hb1 : d_hb0;
        bf16*       hw = (s & 1) ? d_hb0 : d_hb1;
        // phase EA: reduce(s-1) + attention(s) on blocks 0-31
        if (bid < BATCH) {
            if (s > 0) reduce_phase(bid, dec_embed, scratch);
            attn_phase(bid, attn_b, hr, scratch);
        }
        sw_barrier(&g_bar, gen, GRID);
        // phase B: combine (0-15) || logp fixup of step s-1 (16-147)
        if (bid < T_CMB) {
            stage_A<HID, HID>(sA, d_ebuf, d_ctx);
            gemm_tile<2 * HID>(sA, d_Wcmb + (size_t)bid * (2 * HID) * 64, sC, sB);
            int n0 = bid * 64;
            for (int i = threadIdx.x; i < BATCH * 64; i += TPB) {
                int m = i >> 6, j = i & 63;
                float v = sC[m * 64 + j] + comb_b[n0 + j];
                d_inp[m * HID + n0 + j] = __float2bfloat16(fmaxf(v, 0.f));
            }
            __syncthreads();
        } else if (s > 0) {
            fixup_logp(s - 1, out, T_CMB, GRID - T_CMB);
        }
        sw_barrier(&g_bar, gen, GRID);
        // phase C: decoder LSTM gates + cell
        if (bid < T_DEC) {
            stage_A<HID, HID>(sA, d_inp, hr);
            gemm_tile<2 * HID>(sA, d_Wdec + (size_t)bid * (2 * HID) * 64, sC, sB);
            cell_epi(sC, d_bdec, bid * 64, d_cd, hw, nullptr, 0);
        }
        sw_barrier(&g_bar, gen, GRID);
        // phase D: out projection (all blocks)
        stage_A<HID, 0>(sA, hw, nullptr);
        for (int tile = bid; tile < T_OUT; tile += GRID) {
            gemm_tile<HID>(sA, d_Wout + (size_t)tile * HID * 64, sC, sB);
            epi_out(sC, out_b, tile);
        }
        sw_barrier(&g_bar, gen, GRID);
    }
    // tail
    if (bid < BATCH) reduce_phase(bid, dec_embed, scratch);
    sw_barrier(&g_bar, gen, GRID);
    fixup_logp(SEQL - 1, out, 0, GRID);
}

// ---------------- prep ----------------
__global__ void prep_kernel(
    const int* __restrict__ x, const float* __restrict__ enc_embed,
    const float* __restrict__ enc_wx, const float* __restrict__ enc_wh,
    const float* __restrict__ enc_b, const float* __restrict__ dec_embed,
    const float* __restrict__ attn_w, const float* __restrict__ comb_w,
    const float* __restrict__ dec_wx, const float* __restrict__ dec_wh,
    const float* __restrict__ dec_b, const float* __restrict__ out_w)
{
    const size_t gs = (size_t)gridDim.x * blockDim.x;
    const size_t g0 = (size_t)blockIdx.x * blockDim.x + threadIdx.x;

    for (size_t i = g0; i < (size_t)T_ENC * 1536 * 64; i += gs) {
        int tile = (int)(i / 98304); int r = (int)(i % 98304);
        int k = r >> 6, j = r & 63;
        int c = tile * 64 + j, d = c >> 2, g = c & 3, sc = g * HID + d;
        float v = (k < EMBED) ? enc_wx[(size_t)k * G4 + sc]
                              : enc_wh[(size_t)(k - EMBED) * G4 + sc];
        d_Wenc[i] = __float2bfloat16(v);
    }
    for (size_t i = g0; i < (size_t)T_DEC * 2048 * 64; i += gs) {
        int tile = (int)(i / 131072); int r = (int)(i % 131072);
        int k = r >> 6, j = r & 63;
        int c = tile * 64 + j, d = c >> 2, g = c & 3, sc = g * HID + d;
        float v = (k < HID) ? dec_wx[(size_t)k * G4 + sc]
                            : dec_wh[(size_t)(k - HID) * G4 + sc];
        d_Wdec[i] = __float2bfloat16(v);
    }
    for (size_t i = g0; i < (size_t)T_CMB * 2048 * 64; i += gs) {
        int tile = (int)(i / 131072); int r = (int)(i % 131072);
        int k = r >> 6, j = r & 63;
        d_Wcmb[i] = __float2bfloat16(comb_w[(size_t)k * HID + tile * 64 + j]);
    }
    for (size_t i = g0; i < (size_t)T_OUT * HID * 64; i += gs) {
        int tile = (int)(i >> 16); int r = (int)(i & 65535);
        int k = r >> 6, j = r & 63;
        d_Wout[i] = __float2bfloat16(out_w[(size_t)k * VOCAB + tile * 64 + j]);
    }
    for (size_t i = g0; i < (size_t)SEQL * 2 * HID; i += gs) {
        int l = (int)(i >> 11), k = (int)(i & 2047);
        d_attnT[i] = __float2bfloat16(attn_w[(size_t)k * SEQL + l]);
    }
    for (size_t i = g0; i < G4; i += gs) {
        int d = (int)(i >> 2), g = (int)(i & 3);
        d_benc[i] = enc_b[g * HID + d];
        d_bdec[i] = dec_b[g * HID + d];
    }
    for (size_t i = g0; i < BATCH * HID; i += gs) {
        bf16 z = __float2bfloat16(0.f);
        d_gb0[i] = z; d_gb1[i] = z; d_ce[i] = 0.f;
        d_hb0[i] = z; d_hb1[i] = z; d_cd[i] = 0.f;
        d_ebuf[i] = __float2bfloat16(dec_embed[(size_t)127 * HID + (i % HID)]);
    }
    for (size_t i = g0; i < (size_t)SEQL * BATCH * EMBED; i += gs) {
        int t = (int)(i / (BATCH * EMBED));
        int r = (int)(i % (BATCH * EMBED));
        int b = r / EMBED, d = r % EMBED;
        int tok = x[b * SEQL + t];
        d_Eenc[i] = __float2bfloat16(enc_embed[(size_t)tok * EMBED + d]);
    }
    if (g0 == 0) { g_bar = 0u; g_bar_enc = 0u; }
}

// ---------------- host launch ----------------
extern "C" void kernel_launch(void* const* d_in, const int* in_sizes, int n_in,
                              void* d_out, int out_size) {
    (void)in_sizes; (void)n_in; (void)out_size;
    const int*   x         = (const int*)d_in[0];
    const float* enc_embed = (const float*)d_in[1];
    const float* enc_wx    = (const float*)d_in[2];
    const float* enc_wh    = (const float*)d_in[3];
    const float* enc_b     = (const float*)d_in[4];
    const float* dec_embed = (const float*)d_in[5];
    const float* attn_w    = (const float*)d_in[6];
    const float* attn_b    = (const float*)d_in[7];
    const float* comb_w    = (const float*)d_in[8];
    const float* comb_b    = (const float*)d_in[9];
    const float* dec_wx    = (const float*)d_in[10];
    const float* dec_wh    = (const float*)d_in[11];
    const float* dec_b     = (const float*)d_in[12];
    const float* out_w     = (const float*)d_in[13];
    const float* out_b     = (const float*)d_in[14];
    float* out = (float*)d_out;

    cudaFuncSetAttribute(seq_kernel, cudaFuncAttributeMaxDynamicSharedMemorySize, SMEM_DYN);

    prep_kernel<<<2048, TPB>>>(x, enc_embed, enc_wx, enc_wh, enc_b, dec_embed,
                               attn_w, comb_w, dec_wx, dec_wh, dec_b, out_w);
    seq_kernel<<<GRID, TPB, SMEM_DYN>>>(attn_b, comb_b, out_b, dec_embed, out);
}

// round 12
// speedup vs baseline: 1.0222x; 1.0222x over previous
#include <cuda_runtime.h>
#include <cuda_bf16.h>
#include <mma.h>
#include <math.h>

using namespace nvcuda;

#define VOCAB 32000
#define EMBED 512
#define HID   1024      // DEC_H
#define SEQL  64
#define BATCH 32
#define G4    4096
#define GRID  148
#define TPB   256
#define PAD   8

#define T_ENC 64        // G4/64 tiles
#define T_DEC 64
#define T_CMB 16        // HID/64
#define T_OUT 500       // VOCAB/64

#define CH    128                      // K rows per pipeline chunk
#define BSTG  4                        // per-warp ring stages
#define WSL   (CH * 8)                 // per-warp slice elems per chunk (128 rows x 8 cols)
#define SLOT  (8 * WSL)                // all-warp chunk elems (8192)

#define SA_BYTES 131584                // 32 * (2048+8) * 2
#define SB_BYTES (BSTG * SLOT * 2)     // 65536
#define SMEM_DYN (SA_BYTES + SB_BYTES + 32 * 64 * 4)   // 205312

typedef __nv_bfloat16 bf16;

// ---------------- device scratch ----------------
__device__ bf16  d_Eenc[SEQL * BATCH * EMBED];        // [t][b][e] bf16
__device__ bf16  d_enc_outs[BATCH * SEQL * HID];      // [b][t][d] bf16
__device__ bf16  d_gb0[BATCH * HID], d_gb1[BATCH * HID];
__device__ float d_ce[BATCH * HID];
__device__ bf16  d_hb0[BATCH * HID], d_hb1[BATCH * HID];
__device__ float d_cd[BATCH * HID];
__device__ bf16  d_ebuf[BATCH * HID];
__device__ bf16  d_ctx[BATCH * HID];
__device__ bf16  d_inp[BATCH * HID];
__device__ float d_logits[(size_t)BATCH * VOCAB];
__device__ float d_benc[G4], d_bdec[G4];
__device__ float d_pm[BATCH * 512], d_ps[BATCH * 512];
__device__ int   d_pa[BATCH * 512];
__device__ float d_lse[BATCH];

// flag-based barriers: per-block arrival words + one release word
__device__ volatile unsigned d_arr[GRID];
__device__ volatile unsigned d_rel;
__device__ volatile unsigned d_arrE[T_ENC];
__device__ volatile unsigned d_relE;

__device__ bf16 d_attnT[SEQL * 2 * HID];              // attn_w transposed: [l][k] bf16

// weights, warp-sliced layout: [tile][chunk][warp(8col)][128row][8col]
__device__ bf16 d_Wenc[(size_t)T_ENC * (EMBED + HID) * 64];
__device__ bf16 d_Wdec[(size_t)T_DEC * (2 * HID) * 64];
__device__ bf16 d_Wcmb[(size_t)T_CMB * (2 * HID) * 64];
__device__ bf16 d_Wout[(size_t)T_OUT * HID * 64];

__device__ __forceinline__ float sigm(float x) { return 1.f / (1.f + expf(-x)); }

__device__ __forceinline__ float dot8(uint4 ua, uint4 uw) {
    float s = 0.f;
    const unsigned* a = (const unsigned*)&ua;
    const unsigned* w = (const unsigned*)&uw;
    #pragma unroll
    for (int j = 0; j < 4; j++) {
        float2 fa = __bfloat1622float2(*(const __nv_bfloat162*)&a[j]);
        float2 fw = __bfloat1622float2(*(const __nv_bfloat162*)&w[j]);
        s += fa.x * fw.x + fa.y * fw.y;
    }
    return s;
}

// ---------------- cp.async helpers ----------------
__device__ __forceinline__ void cp_async16(bf16* smem_dst, const bf16* gmem_src) {
    unsigned d = (unsigned)__cvta_generic_to_shared(smem_dst);
    asm volatile("cp.async.cg.shared.global [%0], [%1], 16;\n" :: "r"(d), "l"(gmem_src));
}
__device__ __forceinline__ void cp_commit() { asm volatile("cp.async.commit_group;\n"); }
template<int N>
__device__ __forceinline__ void cp_wait() { asm volatile("cp.async.wait_group %0;\n" :: "n"(N)); }

// ---------------- flag-based barrier (no atomics; distinct arrival addrs) ----------------
// All participating blocks (bids 0..nblk-1) call with the same gen sequence.
__device__ __forceinline__ void sw_barrier(volatile unsigned* arr, volatile unsigned* rel,
                                           unsigned& gen, int nblk) {
    const unsigned target = gen + 1u;
    __threadfence();                         // release my data writes
    __syncthreads();
    if (threadIdx.x == 0) arr[blockIdx.x] = target;
    if (blockIdx.x == 0) {
        // master: scan arrivals (one address per thread)
        if ((int)threadIdx.x < nblk) {
            int it = 0;
            while (arr[threadIdx.x] < target) { if (++it > 128) __nanosleep(32); }
        }
        __syncthreads();
        __threadfence();                     // order arrival reads before release write
        if (threadIdx.x == 0) *rel = target;
    }
    if (threadIdx.x == 0) {
        int it = 0;
        while (*rel < target) { if (++it > 128) __nanosleep(32); }
        __threadfence();                     // acquire: invalidate L1D before post-barrier reads
    }
    gen = target;
    __syncthreads();
}

// ---------------- A staging: bf16 copy 32 x (K1+K2) -> smem, ldm = K+PAD ----------------
template<int K1, int K2>
__device__ __forceinline__ void stage_A(bf16* sA, const bf16* __restrict__ A1,
                                        const bf16* __restrict__ A2) {
    constexpr int K = K1 + K2;
    constexpr int tot = 32 * K / 8;
    for (int i = threadIdx.x; i < tot; i += TPB) {
        int m = i / (K / 8);
        int k = (i - m * (K / 8)) * 8;
        const bf16* s = (K2 == 0 || k < K1) ? (A1 + m * K1 + k) : (A2 + m * K2 + (k - K1));
        *(uint4*)(sA + m * (K + PAD) + k) = *(const uint4*)s;
    }
    __syncthreads();
}

// ---------------- warp-decoupled GEMM: sC[32][64] = sA[32][K] @ Bt[K][64] ----------------
// Each warp owns cols [w*8, w*8+8): copies ONLY its slice via per-warp cp.async ring,
// no block syncs in the K loop. Weights pre-tiled: [chunk][warp][128][8].
template<int K>
__device__ __forceinline__ void gemm_tile(const bf16* sA, const bf16* __restrict__ Bt,
                                          float* sC, bf16* sB) {
    constexpr int LDA = K + PAD;
    constexpr int NCH = K / CH;
    const int w = threadIdx.x >> 5;
    const int lane = threadIdx.x & 31;

    // per-warp chunk copy: 128 rows x 16B, 4 segs/lane
    auto copy_chunk = [&](int c, int slot) {
        const bf16* src = Bt + ((size_t)c * 8 + w) * WSL;
        bf16* dst = sB + slot * SLOT + w * WSL;
        #pragma unroll
        for (int i = 0; i < 4; i++) {
            int r = lane + i * 32;
            cp_async16(dst + r * 8, src + r * 8);
        }
        cp_commit();
    };

    #pragma unroll
    for (int st = 0; st < 3; st++) copy_chunk(st, st);

    wmma::fragment<wmma::matrix_a, 32, 8, 16, bf16, wmma::row_major> fa;
    wmma::fragment<wmma::matrix_b, 32, 8, 16, bf16, wmma::row_major> fb;
    wmma::fragment<wmma::accumulator, 32, 8, 16, float> acc0, acc1;
    wmma::fill_fragment(acc0, 0.f);
    wmma::fill_fragment(acc1, 0.f);

    for (int c = 0; c < NCH; c++) {
        cp_wait<2>();              // my groups: chunk c complete
        __syncwarp();
        if (c + 3 < NCH) copy_chunk(c + 3, (c + 3) & 3);
        else cp_commit();          // empty group keeps 1 group/iter accounting
        const bf16* bs = sB + (c & 3) * SLOT + w * WSL;
        const bf16* as = sA + c * CH;
        #pragma unroll
        for (int kk = 0; kk < CH / 16; kk++) {
            wmma::load_matrix_sync(fa, as + kk * 16, LDA);
            wmma::load_matrix_sync(fb, bs + kk * 16 * 8, 8);
            if (kk & 1) wmma::mma_sync(acc1, fa, fb, acc1);
            else        wmma::mma_sync(acc0, fa, fb, acc0);
        }
    }
    cp_wait<0>();
    #pragma unroll
    for (int i = 0; i < acc0.num_elements; i++) acc0.x[i] += acc1.x[i];
    wmma::store_matrix_sync(sC + w * 8, acc0, 64, wmma::mem_row_major);
    __syncthreads();               // sC complete for epilogue
}

// ---------------- LSTM cell epilogue (interleaved gates, tile n0) ----------------
__device__ __forceinline__ void cell_epi(const float* sC, const float* bias, int n0,
                                         float* cbuf, bf16* hb, bf16* enc_out, int t) {
    for (int i = threadIdx.x; i < BATCH * 16; i += TPB) {
        int m = i >> 4, dd = i & 15, cb = dd * 4;
        float gi = sigm(sC[m * 64 + cb + 0] + bias[n0 + cb + 0]);
        float gf = sigm(sC[m * 64 + cb + 1] + bias[n0 + cb + 1]);
        float gg = tanhf(sC[m * 64 + cb + 2] + bias[n0 + cb + 2]);
        float go = sigm(sC[m * 64 + cb + 3] + bias[n0 + cb + 3]);
        int d = (n0 >> 2) + dd;
        int idx = m * HID + d;
        float c = gf * cbuf[idx] + gi * gg;
        float h = go * tanhf(c);
        cbuf[idx] = c;
        bf16 hb16 = __float2bfloat16(h);
        hb[idx] = hb16;
        if (enc_out) enc_out[((size_t)m * SEQL + t) * HID + d] = hb16;
    }
    __syncthreads();
}

// ---------------- out-projection epilogue: logits + online-softmax partials ----------------
__device__ __forceinline__ void epi_out(const float* sC, const float* __restrict__ out_b, int tile) {
    const int tid = threadIdx.x;
    const int r = tid >> 3, c0 = (tid & 7) * 8, n0 = tile * 64;
    float v[8];
    float pm = -INFINITY; int pa = 0;
    #pragma unroll
    for (int j = 0; j < 8; j++) {
        float x = sC[r * 64 + c0 + j] + out_b[n0 + c0 + j];
        v[j] = x;
        if (x > pm) { pm = x; pa = n0 + c0 + j; }
    }
    float4* dst = (float4*)(d_logits + (size_t)r * VOCAB + n0 + c0);
    dst[0] = make_float4(v[0], v[1], v[2], v[3]);
    dst[1] = make_float4(v[4], v[5], v[6], v[7]);
    float ps = 0.f;
    #pragma unroll
    for (int j = 0; j < 8; j++) ps += expf(v[j] - pm);
    #pragma unroll
    for (int o = 4; o > 0; o >>= 1) {
        float om = __shfl_xor_sync(0xffffffffu, pm, o);
        float os = __shfl_xor_sync(0xffffffffu, ps, o);
        int   oa = __shfl_xor_sync(0xffffffffu, pa, o);
        if (om > pm) { ps = ps * expf(pm - om) + os; pm = om; pa = oa; }
        else if (om == pm) { ps += os; if (oa < pa) pa = oa; }
        else ps += os * expf(om - pm);
    }
    if ((tid & 7) == 0) {
        d_pm[r * 512 + tile] = pm;
        d_ps[r * 512 + tile] = ps;
        d_pa[r * 512 + tile] = pa;
    }
    __syncthreads();
}

// ---------------- attention: logits + softmax + context for batch b ----------------
__device__ void attn_phase(int b, const float* __restrict__ attn_b,
                           const bf16* __restrict__ hb, float* scratch) {
    float* aw = scratch;   // 64 floats
    const int tid = threadIdx.x;
    const int l = tid >> 2, part = tid & 3;
    const bf16* e = d_ebuf + b * HID;
    const bf16* h = hb + b * HID;
    const uint4* wrow = (const uint4*)(d_attnT + (size_t)l * 2 * HID + part * 512);
    const uint4* av = (const uint4*)((part < 2) ? (e + part * 512) : (h + (part - 2) * 512));
    float s = 0.f;
    #pragma unroll 8
    for (int i = 0; i < 64; i++) s += dot8(av[i], wrow[i]);
    s += __shfl_xor_sync(0xffffffffu, s, 1);
    s += __shfl_xor_sync(0xffffffffu, s, 2);
    if (part == 0) aw[l] = s + attn_b[l];
    __syncthreads();
    if (tid == 0) {
        float mx = -INFINITY;
        for (int j = 0; j < SEQL; j++) mx = fmaxf(mx, aw[j]);
        float sum = 0.f;
        for (int j = 0; j < SEQL; j++) { float ev = expf(aw[j] - mx); aw[j] = ev; sum += ev; }
        float inv = 1.f / sum;
        for (int j = 0; j < SEQL; j++) aw[j] *= inv;
    }
    __syncthreads();
    const bf16* eo = d_enc_outs + (size_t)b * SEQL * HID;
    const int d4 = tid * 4;
    float c0 = 0.f, c1 = 0.f, c2 = 0.f, c3 = 0.f;
    #pragma unroll 8
    for (int ll = 0; ll < SEQL; ll++) {
        float a = aw[ll];
        uint2 u = *(const uint2*)(eo + (size_t)ll * HID + d4);
        float2 p0 = __bfloat1622float2(*(const __nv_bfloat162*)&u.x);
        float2 p1 = __bfloat1622float2(*(const __nv_bfloat162*)&u.y);
        c0 += a * p0.x; c1 += a * p0.y; c2 += a * p1.x; c3 += a * p1.y;
    }
    __nv_bfloat162 o0 = __floats2bfloat162_rn(c0, c1);
    __nv_bfloat162 o1 = __floats2bfloat162_rn(c2, c3);
    uint2 uo; uo.x = *(unsigned*)&o0; uo.y = *(unsigned*)&o1;
    *(uint2*)(d_ctx + b * HID + d4) = uo;
    __syncthreads();
}

// ---------------- reduce partials -> lse, argmax token, gather next embedding ----------------
__device__ void reduce_phase(int b, const float* __restrict__ dec_embed, float* scratch) {
    const int tid = threadIdx.x;
    float* smax = scratch;
    float* ssum = scratch + 256;
    int*   sarg = (int*)(scratch + 512);
    int*   stok = (int*)(scratch + 768);
    float pm = -INFINITY, ps = 0.f; int pa = 0;
    for (int t = tid; t < T_OUT; t += TPB) {
        float om = d_pm[b * 512 + t], os = d_ps[b * 512 + t];
        int oa = d_pa[b * 512 + t];
        if (om > pm) { ps = ps * expf(pm - om) + os; pm = om; pa = oa; }
        else if (om == pm) { ps += os; if (oa < pa) pa = oa; }
        else ps += os * expf(om - pm);
    }
    smax[tid] = pm; ssum[tid] = ps; sarg[tid] = pa;
    __syncthreads();
    for (int st = 128; st > 0; st >>= 1) {
        if (tid < st) {
            float om = smax[tid + st], os = ssum[tid + st]; int oa = sarg[tid + st];
            float cm = smax[tid],      cs = ssum[tid];      int ca = sarg[tid];
            if (om > cm) { cs = cs * expf(cm - om) + os; cm = om; ca = oa; }
            else if (om == cm) { cs += os; if (oa < ca) ca = oa; }
            else cs += os * expf(om - cm);
            smax[tid] = cm; ssum[tid] = cs; sarg[tid] = ca;
        }
        __syncthreads();
    }
    if (tid == 0) { d_lse[b] = smax[0] + logf(ssum[0]); stok[0] = sarg[0]; }
    __syncthreads();
    int token = stok[0];
    for (int d = tid; d < HID; d += TPB)
        d_ebuf[b * HID + d] = __float2bfloat16(dec_embed[(size_t)token * HID + d]);
    __syncthreads();
}

// ---------------- distributed log-p write ----------------
__device__ void fixup_logp(int step, float* __restrict__ out, int bfirst, int nblocks) {
    int lb = blockIdx.x - bfirst;
    const int tot = BATCH * (VOCAB / 4);
    for (int i = lb * TPB + threadIdx.x; i < tot; i += nblocks * TPB) {
        int b = i / (VOCAB / 4);
        int q = i - b * (VOCAB / 4);
        float4 f = ((const float4*)(d_logits + (size_t)b * VOCAB))[q];
        float lse = d_lse[b];
        f.x -= lse; f.y -= lse; f.z -= lse; f.w -= lse;
        ((float4*)(out + ((size_t)b * SEQL + step) * VOCAB))[q] = f;
    }
}

// ---------------- persistent kernel ----------------
__global__ __launch_bounds__(TPB, 1) void seq_kernel(
    const float* __restrict__ attn_b,
    const float* __restrict__ comb_b, const float* __restrict__ out_b,
    const float* __restrict__ dec_embed, float* __restrict__ out)
{
    extern __shared__ unsigned char dynmem[];
    bf16*  sA = (bf16*)dynmem;
    bf16*  sB = (bf16*)(dynmem + SA_BYTES);
    float* sC = (float*)(dynmem + SA_BYTES + SB_BYTES);
    float* scratch = (float*)sA;
    unsigned gen = 0, gen_enc = 0;
    const int bid = blockIdx.x;

    // ---- encoder: blocks 0-63, flag sub-barrier ----
    if (bid < T_ENC) {
        for (int t = 0; t < SEQL; t++) {
            const bf16* hr = (t & 1) ? d_gb1 : d_gb0;
            bf16*       hw = (t & 1) ? d_gb0 : d_gb1;
            stage_A<EMBED, HID>(sA, d_Eenc + (size_t)t * BATCH * EMBED, hr);
            gemm_tile<EMBED + HID>(sA, d_Wenc + (size_t)bid * (EMBED + HID) * 64, sC, sB);
            cell_epi(sC, d_benc, bid * 64, d_ce, hw, d_enc_outs, t);
            sw_barrier(d_arrE, &d_relE, gen_enc, T_ENC);
        }
    }
    sw_barrier(d_arr, &d_rel, gen, GRID);

    // ---- decoder ----
    for (int s = 0; s < SEQL; s++) {
        const bf16* hr = (s & 1) ? d_hb1 : d_hb0;
        bf16*       hw = (s & 1) ? d_hb0 : d_hb1;
        // phase EA: reduce(s-1) + attention(s) on blocks 0-31
        if (bid < BATCH) {
            if (s > 0) reduce_phase(bid, dec_embed, scratch);
            attn_phase(bid, attn_b, hr, scratch);
        }
        sw_barrier(d_arr, &d_rel, gen, GRID);
        // phase B: combine (0-15) || logp fixup of step s-1 (16-147)
        if (bid < T_CMB) {
            stage_A<HID, HID>(sA, d_ebuf, d_ctx);
            gemm_tile<2 * HID>(sA, d_Wcmb + (size_t)bid * (2 * HID) * 64, sC, sB);
            int n0 = bid * 64;
            for (int i = threadIdx.x; i < BATCH * 64; i += TPB) {
                int m = i >> 6, j = i & 63;
                float v = sC[m * 64 + j] + comb_b[n0 + j];
                d_inp[m * HID + n0 + j] = __float2bfloat16(fmaxf(v, 0.f));
            }
            __syncthreads();
        } else if (s > 0) {
            fixup_logp(s - 1, out, T_CMB, GRID - T_CMB);
        }
        sw_barrier(d_arr, &d_rel, gen, GRID);
        // phase C: decoder LSTM gates + cell
        if (bid < T_DEC) {
            stage_A<HID, HID>(sA, d_inp, hr);
            gemm_tile<2 * HID>(sA, d_Wdec + (size_t)bid * (2 * HID) * 64, sC, sB);
            cell_epi(sC, d_bdec, bid * 64, d_cd, hw, nullptr, 0);
        }
        sw_barrier(d_arr, &d_rel, gen, GRID);
        // phase D: out projection, balanced (blocks 0-91: 3 tiles; 92-147: 4 tiles)
        stage_A<HID, 0>(sA, hw, nullptr);
        int t0, nt;
        if (bid < 92) { t0 = bid * 3;              nt = 3; }
        else          { t0 = 276 + (bid - 92) * 4; nt = 4; }
        for (int i = 0; i < nt; i++) {
            int tile = t0 + i;
            gemm_tile<HID>(sA, d_Wout + (size_t)tile * HID * 64, sC, sB);
            epi_out(sC, out_b, tile);
        }
        sw_barrier(d_arr, &d_rel, gen, GRID);
    }
    // tail
    if (bid < BATCH) reduce_phase(bid, dec_embed, scratch);
    sw_barrier(d_arr, &d_rel, gen, GRID);
    fixup_logp(SEQL - 1, out, 0, GRID);
}

// ---------------- prep ----------------
// warp-sliced weight layout: i = (((tile*NCH + c)*8 + w)*CH + r)*8 + j
//   k = c*CH + r ; col-in-tile = w*8 + j
__global__ void prep_kernel(
    const int* __restrict__ x, const float* __restrict__ enc_embed,
    const float* __restrict__ enc_wx, const float* __restrict__ enc_wh,
    const float* __restrict__ enc_b, const float* __restrict__ dec_embed,
    const float* __restrict__ attn_w, const float* __restrict__ comb_w,
    const float* __restrict__ dec_wx, const float* __restrict__ dec_wh,
    const float* __restrict__ dec_b, const float* __restrict__ out_w)
{
    const size_t gs = (size_t)gridDim.x * blockDim.x;
    const size_t g0 = (size_t)blockIdx.x * blockDim.x + threadIdx.x;

    // Wenc: K=1536, NCH=12, gate-interleaved cols
    for (size_t i = g0; i < (size_t)T_ENC * 1536 * 64; i += gs) {
        int j = (int)(i & 7), r = (int)((i >> 3) & 127), w = (int)((i >> 10) & 7);
        int cc = (int)(i >> 13);
        int c = cc % 12, tile = cc / 12;
        int k = c * CH + r;
        int col = tile * 64 + w * 8 + j;
        int d = col >> 2, g = col & 3, sc = g * HID + d;
        float v = (k < EMBED) ? enc_wx[(size_t)k * G4 + sc]
                              : enc_wh[(size_t)(k - EMBED) * G4 + sc];
        d_Wenc[i] = __float2bfloat16(v);
    }
    // Wdec: K=2048, NCH=16, gate-interleaved
    for (size_t i = g0; i < (size_t)T_DEC * 2048 * 64; i += gs) {
        int j = (int)(i & 7), r = (int)((i >> 3) & 127), w = (int)((i >> 10) & 7);
        int cc = (int)(i >> 13);
        int c = cc & 15, tile = cc >> 4;
        int k = c * CH + r;
        int col = tile * 64 + w * 8 + j;
        int d = col >> 2, g = col & 3, sc = g * HID + d;
        float v = (k < HID) ? dec_wx[(size_t)k * G4 + sc]
                            : dec_wh[(size_t)(k - HID) * G4 + sc];
        d_Wdec[i] = __float2bfloat16(v);
    }
    // Wcmb: K=2048, NCH=16, plain cols
    for (size_t i = g0; i < (size_t)T_CMB * 2048 * 64; i += gs) {
        int j = (int)(i & 7), r = (int)((i >> 3) & 127), w = (int)((i >> 10) & 7);
        int cc = (int)(i >> 13);
        int c = cc & 15, tile = cc >> 4;
        int k = c * CH + r;
        int col = tile * 64 + w * 8 + j;
        d_Wcmb[i] = __float2bfloat16(comb_w[(size_t)k * HID + col]);
    }
    // Wout: K=1024, NCH=8, plain cols
    for (size_t i = g0; i < (size_t)T_OUT * HID * 64; i += gs) {
        int j = (int)(i & 7), r = (int)((i >> 3) & 127), w = (int)((i >> 10) & 7);
        int cc = (int)(i >> 13);
        int c = cc & 7, tile = cc >> 3;
        int k = c * CH + r;
        int col = tile * 64 + w * 8 + j;
        d_Wout[i] = __float2bfloat16(out_w[(size_t)k * VOCAB + col]);
    }
    // attn_w transpose -> [l][k] bf16
    for (size_t i = g0; i < (size_t)SEQL * 2 * HID; i += gs) {
        int l = (int)(i >> 11), k = (int)(i & 2047);
        d_attnT[i] = __float2bfloat16(attn_w[(size_t)k * SEQL + l]);
    }
    // interleaved biases
    for (size_t i = g0; i < G4; i += gs) {
        int d = (int)(i >> 2), g = (int)(i & 3);
        d_benc[i] = enc_b[g * HID + d];
        d_bdec[i] = dec_b[g * HID + d];
    }
    // states + initial decoder embedding (token 127)
    for (size_t i = g0; i < BATCH * HID; i += gs) {
        bf16 z = __float2bfloat16(0.f);
        d_gb0[i] = z; d_gb1[i] = z; d_ce[i] = 0.f;
        d_hb0[i] = z; d_hb1[i] = z; d_cd[i] = 0.f;
        d_ebuf[i] = __float2bfloat16(dec_embed[(size_t)127 * HID + (i % HID)]);
    }
    // gather encoder embeddings [t][b][e] bf16
    for (size_t i = g0; i < (size_t)SEQL * BATCH * EMBED; i += gs) {
        int t = (int)(i / (BATCH * EMBED));
        int r = (int)(i % (BATCH * EMBED));
        int b = r / EMBED, d = r % EMBED;
        int tok = x[b * SEQL + t];
        d_Eenc[i] = __float2bfloat16(enc_embed[(size_t)tok * EMBED + d]);
    }
    // barrier state
    if (g0 < GRID) d_arr[g0] = 0u;
    if (g0 < T_ENC) d_arrE[g0] = 0u;
    if (g0 == 0) { d_rel = 0u; d_relE = 0u; }
}

// ---------------- host launch ----------------
extern "C" void kernel_launch(void* const* d_in, const int* in_sizes, int n_in,
                              void* d_out, int out_size) {
    (void)in_sizes; (void)n_in; (void)out_size;
    const int*   x         = (const int*)d_in[0];
    const float* enc_embed = (const float*)d_in[1];
    const float* enc_wx    = (const float*)d_in[2];
    const float* enc_wh    = (const float*)d_in[3];
    const float* enc_b     = (const float*)d_in[4];
    const float* dec_embed = (const float*)d_in[5];
    const float* attn_w    = (const float*)d_in[6];
    const float* attn_b    = (const float*)d_in[7];
    const float* comb_w    = (const float*)d_in[8];
    const float* comb_b    = (const float*)d_in[9];
    const float* dec_wx    = (const float*)d_in[10];
    const float* dec_wh    = (const float*)d_in[11];
    const float* dec_b     = (const float*)d_in[12];
    const float* out_w     = (const float*)d_in[13];
    const float* out_b     = (const float*)d_in[14];
    float* out = (float*)d_out;

    cudaFuncSetAttribute(seq_kernel, cudaFuncAttributeMaxDynamicSharedMemorySize, SMEM_DYN);

    prep_kernel<<<2048, TPB>>>(x, enc_embed, enc_wx, enc_wh, enc_b, dec_embed,
                               attn_w, comb_w, dec_wx, dec_wh, dec_b, out_w);
    seq_kernel<<<GRID, TPB, SMEM_DYN>>>(attn_b, comb_b, out_b, dec_embed, out);
}